// round 1
// baseline (speedup 1.0000x reference)
#include <cuda_runtime.h>
#include <cuda_bf16.h>
#include <math.h>

// Problem constants (fixed shapes from setup_inputs)
#define BB   8
#define NN   4096      // 64*64
#define DD   256
#define NH   8
#define NP   4
#define HD   32
#define MM   (BB*NN)   // 32768 rows
#define NCAT 384       // 256 (v) + 64 (off) + 32 (attw) + 32 pad

// ---------------- scratch (device globals; no allocations allowed) ----------
__device__ float g_wcat[DD * NCAT];          // packed [K=256, N=384] weights
__device__ float g_bcat[NCAT];               // packed bias
__device__ float g_y[(size_t)MM * NCAT];     // stage-1 output: v | off_raw | attw_raw
__device__ float g_mid[(size_t)MM * DD];     // sampled+weighted output

// ---------------- weight packing ----------------
__global__ void pack_kernel(const float* __restrict__ qkv_w, const float* __restrict__ qkv_b,
                            const float* __restrict__ off_w, const float* __restrict__ off_b,
                            const float* __restrict__ attw_w, const float* __restrict__ attw_b)
{
    int idx = blockIdx.x * blockDim.x + threadIdx.x;
    if (idx < DD * NCAT) {
        int k = idx / NCAT, j = idx % NCAT;
        float v;
        if (j < 256)      v = qkv_w[k * 768 + 512 + j];
        else if (j < 320) v = off_w[k * 64 + (j - 256)];
        else if (j < 352) v = attw_w[k * 32 + (j - 320)];
        else              v = 0.0f;
        g_wcat[k * NCAT + j] = v;
    }
    if (idx < NCAT) {
        float bv;
        if (idx < 256)      bv = qkv_b[512 + idx];
        else if (idx < 320) bv = off_b[idx - 256];
        else if (idx < 352) bv = attw_b[idx - 320];
        else                bv = 0.0f;
        g_bcat[idx] = bv;
    }
}

// ---------------- SGEMM: C[M,N] = A[M,K] @ B[K,N] + bias ----------------
// BM=BN=128, BK=8, 256 threads, each thread 8x8 as 2x2 grid of 4x4 subtiles.
template <int N>
__device__ __forceinline__ void sgemm_body(const float* __restrict__ A,
                                           const float* __restrict__ B,
                                           const float* __restrict__ bias,
                                           float* __restrict__ C)
{
    constexpr int K = DD;   // 256
    __shared__ float As[8][128];
    __shared__ float Bs[8][128];

    const int tid = threadIdx.x;
    const int m0 = blockIdx.y * 128;
    const int n0 = blockIdx.x * 128;

    const int a_row = tid >> 1;            // 0..127
    const int a_col = (tid & 1) * 4;       // 0 or 4
    const int b_row = tid >> 5;            // 0..7
    const int b_col = (tid & 31) * 4;      // 0..124

    const int tx = tid & 15;               // 0..15
    const int ty = tid >> 4;               // 0..15

    float acc[8][8];
#pragma unroll
    for (int i = 0; i < 8; ++i)
#pragma unroll
        for (int j = 0; j < 8; ++j) acc[i][j] = 0.0f;

    for (int k0 = 0; k0 < K; k0 += 8) {
        float4 av = *reinterpret_cast<const float4*>(A + (size_t)(m0 + a_row) * K + k0 + a_col);
        As[a_col + 0][a_row] = av.x;
        As[a_col + 1][a_row] = av.y;
        As[a_col + 2][a_row] = av.z;
        As[a_col + 3][a_row] = av.w;
        *reinterpret_cast<float4*>(&Bs[b_row][b_col]) =
            *reinterpret_cast<const float4*>(B + (size_t)(k0 + b_row) * N + n0 + b_col);
        __syncthreads();

#pragma unroll
        for (int k = 0; k < 8; ++k) {
            float4 a0 = *reinterpret_cast<const float4*>(&As[k][ty * 4]);
            float4 a1 = *reinterpret_cast<const float4*>(&As[k][64 + ty * 4]);
            float4 b0 = *reinterpret_cast<const float4*>(&Bs[k][tx * 4]);
            float4 b1 = *reinterpret_cast<const float4*>(&Bs[k][64 + tx * 4]);
            float ar[8] = {a0.x, a0.y, a0.z, a0.w, a1.x, a1.y, a1.z, a1.w};
            float br[8] = {b0.x, b0.y, b0.z, b0.w, b1.x, b1.y, b1.z, b1.w};
#pragma unroll
            for (int i = 0; i < 8; ++i)
#pragma unroll
                for (int j = 0; j < 8; ++j)
                    acc[i][j] += ar[i] * br[j];
        }
        __syncthreads();
    }

#pragma unroll
    for (int ih = 0; ih < 2; ++ih) {
#pragma unroll
        for (int i = 0; i < 4; ++i) {
            int row = m0 + ih * 64 + ty * 4 + i;
#pragma unroll
            for (int jh = 0; jh < 2; ++jh) {
                int col = n0 + jh * 64 + tx * 4;
                float4 o;
                o.x = acc[ih * 4 + i][jh * 4 + 0] + bias[col + 0];
                o.y = acc[ih * 4 + i][jh * 4 + 1] + bias[col + 1];
                o.z = acc[ih * 4 + i][jh * 4 + 2] + bias[col + 2];
                o.w = acc[ih * 4 + i][jh * 4 + 3] + bias[col + 3];
                *reinterpret_cast<float4*>(C + (size_t)row * N + col) = o;
            }
        }
    }
}

__global__ __launch_bounds__(256) void gemm1_kernel(const float* __restrict__ x)
{
    sgemm_body<NCAT>(x, g_wcat, g_bcat, g_y);
}

__global__ __launch_bounds__(256) void gemm2_kernel(const float* __restrict__ proj_w,
                                                    const float* __restrict__ proj_b,
                                                    float* __restrict__ out)
{
    sgemm_body<DD>(g_mid, proj_w, proj_b, out);
}

// ---------------- deformable sampling ----------------
// One warp per (b, n, h); lane = channel c (0..31).
__global__ __launch_bounds__(256) void sample_kernel()
{
    int gw = (blockIdx.x * blockDim.x + threadIdx.x) >> 5;   // 0 .. B*N*nh-1
    int lane = threadIdx.x & 31;

    int h = gw & 7;
    int n = (gw >> 3) & (NN - 1);
    int b = gw >> 15;

    const float* yrow = g_y + (size_t)(b * NN + n) * NCAT;

    // raw offsets (8) and raw attn logits (4) for this head
    float offr[8];
#pragma unroll
    for (int t = 0; t < 8; ++t) offr[t] = yrow[256 + h * 8 + t];
    float aw[4];
#pragma unroll
    for (int p = 0; p < NP; ++p) aw[p] = yrow[320 + h * 4 + p];

    // softmax over P
    float mx = fmaxf(fmaxf(aw[0], aw[1]), fmaxf(aw[2], aw[3]));
    float s = 0.0f;
#pragma unroll
    for (int p = 0; p < NP; ++p) { aw[p] = __expf(aw[p] - mx); s += aw[p]; }
    float inv = 1.0f / s;

    float px = (float)(n & 63);
    float py = (float)(n >> 6);

    const float* vbase = g_y + (size_t)b * NN * NCAT + h * HD + lane;

    float acc = 0.0f;
#pragma unroll
    for (int p = 0; p < NP; ++p) {
        float gx = px + 2.0f * tanhf(offr[2 * p]);
        float gy = py + 2.0f * tanhf(offr[2 * p + 1]);
        float x0f = floorf(gx), y0f = floorf(gy);
        int x0 = (int)x0f, y0 = (int)y0f;
        int x1 = x0 + 1, y1 = y0 + 1;
        float wx1 = gx - x0f, wy1 = gy - y0f;
        float wx0 = 1.0f - wx1, wy0 = 1.0f - wy1;
        float ap = aw[p] * inv;

        float c00 = ap * wx0 * wy0;
        float c10 = ap * wx1 * wy0;
        float c01 = ap * wx0 * wy1;
        float c11 = ap * wx1 * wy1;

        if (x0 >= 0 && x0 < 64 && y0 >= 0 && y0 < 64)
            acc += c00 * vbase[(size_t)(y0 * 64 + x0) * NCAT];
        if (x1 >= 0 && x1 < 64 && y0 >= 0 && y0 < 64)
            acc += c10 * vbase[(size_t)(y0 * 64 + x1) * NCAT];
        if (x0 >= 0 && x0 < 64 && y1 >= 0 && y1 < 64)
            acc += c01 * vbase[(size_t)(y1 * 64 + x0) * NCAT];
        if (x1 >= 0 && x1 < 64 && y1 >= 0 && y1 < 64)
            acc += c11 * vbase[(size_t)(y1 * 64 + x1) * NCAT];
    }

    g_mid[(size_t)(b * NN + n) * DD + h * HD + lane] = acc;
}

// ---------------- launch ----------------
extern "C" void kernel_launch(void* const* d_in, const int* in_sizes, int n_in,
                              void* d_out, int out_size)
{
    const float* x      = (const float*)d_in[0];
    const float* qkv_w  = (const float*)d_in[1];
    const float* qkv_b  = (const float*)d_in[2];
    const float* off_w  = (const float*)d_in[3];
    const float* off_b  = (const float*)d_in[4];
    const float* attw_w = (const float*)d_in[5];
    const float* attw_b = (const float*)d_in[6];
    const float* proj_w = (const float*)d_in[7];
    const float* proj_b = (const float*)d_in[8];
    float* out = (float*)d_out;

    // 1) pack weights/bias for fused stage-1 GEMM
    pack_kernel<<<(DD * NCAT + 255) / 256, 256>>>(qkv_w, qkv_b, off_w, off_b, attw_w, attw_b);

    // 2) stage-1 GEMM: X[32768,256] @ Wcat[256,384] -> Y (v | off_raw | attw_raw)
    gemm1_kernel<<<dim3(NCAT / 128, MM / 128), 256>>>(x);

    // 3) deformable bilinear sampling + softmax-weighted accumulation
    //    one warp per (b,n,h): 262144 warps -> 32768 blocks of 8 warps
    sample_kernel<<<(BB * NN * NH) / 8, 256>>>();

    // 4) output projection: mid[32768,256] @ proj_w[256,256] + proj_b
    gemm2_kernel<<<dim3(DD / 128, MM / 128), 256>>>(proj_w, proj_b, out);
}

// round 3
// speedup vs baseline: 1.4794x; 1.4794x over previous
#include <cuda_runtime.h>
#include <cuda_bf16.h>
#include <cstdint>
#include <math.h>

// Problem constants (fixed shapes from setup_inputs)
#define BB   8
#define NN   4096      // 64*64
#define DD   256
#define NH   8
#define NP   4
#define HD   32
#define MM   (BB*NN)   // 32768 rows
#define NCAT 384       // 256 (v) + 64 (off) + 32 (attw) + 32 pad

// ---------------- scratch (device globals; no allocations allowed) ----------
__device__ float g_y[(size_t)MM * NCAT];          // stage-1 output: v | off | attw
__device__ float g_bcat[NCAT];                    // packed stage-1 bias
__device__ __nv_bfloat16 g_xh[(size_t)MM * DD];   // x split hi
__device__ __nv_bfloat16 g_xl[(size_t)MM * DD];   // x split lo
__device__ __nv_bfloat16 g_midh[(size_t)MM * DD]; // sampled output split hi
__device__ __nv_bfloat16 g_midl[(size_t)MM * DD]; // sampled output split lo
__device__ __nv_bfloat16 g_w1h[DD * NCAT];        // [k][n] stage-1 weights hi
__device__ __nv_bfloat16 g_w1l[DD * NCAT];
__device__ __nv_bfloat16 g_w2h[DD * DD];          // [k][n] proj weights hi
__device__ __nv_bfloat16 g_w2l[DD * DD];

// =================== helpers ===================
__device__ __forceinline__ uint32_t smem_to_u32(const void* p) {
    uint32_t a;
    asm("{ .reg .u64 t; cvta.to.shared.u64 t, %1; cvt.u32.u64 %0, t; }" : "=r"(a) : "l"(p));
    return a;
}
__device__ __forceinline__ void split_bf16(float w, __nv_bfloat16& h, __nv_bfloat16& l) {
    h = __float2bfloat16_rn(w);
    l = __float2bfloat16_rn(w - __bfloat162float(h));
}
__device__ __forceinline__ void cp_async16(uint32_t dst, const void* src) {
    asm volatile("{ .reg .u64 g; cvta.to.global.u64 g, %1; cp.async.cg.shared.global [%0], [g], 16; }"
                 :: "r"(dst), "l"(src));
}
template <int N>
__device__ __forceinline__ void cp_wait() {
    asm volatile("cp.async.wait_group %0;" :: "n"(N));
}
__device__ __forceinline__ void cp_commit() {
    asm volatile("cp.async.commit_group;");
}
__device__ __forceinline__ void ldsm_x4(uint32_t (&r)[4], uint32_t addr) {
    asm volatile("ldmatrix.sync.aligned.m8n8.x4.shared.b16 {%0,%1,%2,%3}, [%4];"
                 : "=r"(r[0]), "=r"(r[1]), "=r"(r[2]), "=r"(r[3]) : "r"(addr));
}
__device__ __forceinline__ void ldsm_x2t(uint32_t (&r)[2], uint32_t addr) {
    asm volatile("ldmatrix.sync.aligned.m8n8.x2.trans.shared.b16 {%0,%1}, [%2];"
                 : "=r"(r[0]), "=r"(r[1]) : "r"(addr));
}
__device__ __forceinline__ void mma_bf16(float (&c)[4], const uint32_t (&a)[4], const uint32_t (&b)[2]) {
    asm volatile("mma.sync.aligned.m16n8k16.row.col.f32.bf16.bf16.f32 "
                 "{%0,%1,%2,%3}, {%4,%5,%6,%7}, {%8,%9}, {%0,%1,%2,%3};"
                 : "+f"(c[0]), "+f"(c[1]), "+f"(c[2]), "+f"(c[3])
                 : "r"(a[0]), "r"(a[1]), "r"(a[2]), "r"(a[3]), "r"(b[0]), "r"(b[1]));
}

// =================== pack kernels ===================
__global__ void pack_x_kernel(const float* __restrict__ x)
{
    int idx = blockIdx.x * blockDim.x + threadIdx.x;
    if (idx < MM * DD) {
        __nv_bfloat16 h, l; split_bf16(x[idx], h, l);
        g_xh[idx] = h; g_xl[idx] = l;
    }
}

__global__ void pack_w1_kernel(const float* __restrict__ qkv_w, const float* __restrict__ qkv_b,
                               const float* __restrict__ off_w, const float* __restrict__ off_b,
                               const float* __restrict__ attw_w, const float* __restrict__ attw_b)
{
    int idx = blockIdx.x * blockDim.x + threadIdx.x;   // over DD*NCAT, idx = k*384 + n
    if (idx < DD * NCAT) {
        int k = idx / NCAT, n = idx % NCAT;
        float w;
        if (n < 256)      w = qkv_w[k * 768 + 512 + n];
        else if (n < 320) w = off_w[k * 64 + (n - 256)];
        else if (n < 352) w = attw_w[k * 32 + (n - 320)];
        else              w = 0.0f;
        __nv_bfloat16 h, l; split_bf16(w, h, l);
        g_w1h[idx] = h; g_w1l[idx] = l;
    }
    if (idx < NCAT) {
        float bv;
        if (idx < 256)      bv = qkv_b[512 + idx];
        else if (idx < 320) bv = off_b[idx - 256];
        else if (idx < 352) bv = attw_b[idx - 320];
        else                bv = 0.0f;
        g_bcat[idx] = bv;
    }
}

__global__ void pack_w2_kernel(const float* __restrict__ proj_w)
{
    int idx = blockIdx.x * blockDim.x + threadIdx.x;   // proj_w already [k][n]
    if (idx < DD * DD) {
        __nv_bfloat16 h, l; split_bf16(proj_w[idx], h, l);
        g_w2h[idx] = h; g_w2l[idx] = l;
    }
}

// =================== mma.sync bf16x3 GEMM ===================
// C[M, Nw] = A[M,256] @ B[256, Nw] + bias   (A = Ah+Al, B = Bh+Bl bf16 splits)
// CTA tile 128x64, BK=32, 256 threads, warp tile 32x32 (4x2 warp grid).
// SMEM per stage: Ah[128][56h] Al[...] Bh[32][72h] Bl[...]; double buffered.
#define A_ROW_B   112                       // bytes per A smem row (56 halves)
#define B_ROW_B   144                       // bytes per B smem row (72 halves)
#define SM_AL_OFF 14336                     // 128*112
#define SM_BH_OFF 28672
#define SM_BL_OFF 33280                     // +32*144
#define SM_STAGE  37888
#define SMEM_GEMM_SZ (2 * SM_STAGE)

__device__ __forceinline__ void mma_gemm_body(const __nv_bfloat16* __restrict__ Ah,
                                              const __nv_bfloat16* __restrict__ Al,
                                              const __nv_bfloat16* __restrict__ Bh,
                                              const __nv_bfloat16* __restrict__ Bl,
                                              const float* __restrict__ bias,
                                              float* __restrict__ C, int Nw)
{
    extern __shared__ char smem[];
    const uint32_t sm = smem_to_u32(smem);
    const int tid = threadIdx.x;
    const int lane = tid & 31, wid = tid >> 5;
    const int warp_m = wid >> 1, warp_n = wid & 1;
    const int m0 = blockIdx.y * 128, n0 = blockIdx.x * 64;

    // per-thread cp.async chunk assignments (fixed across stages)
    const __nv_bfloat16* a_src[4]; uint32_t a_dst[4];
#pragma unroll
    for (int i = 0; i < 4; ++i) {
        int c = tid + i * 256;
        int mat = c >> 9, cc = c & 511, row = cc >> 2, kc = cc & 3;
        a_src[i] = (mat ? Al : Ah) + (size_t)(m0 + row) * DD + kc * 8;
        a_dst[i] = sm + mat * SM_AL_OFF + row * A_ROW_B + kc * 16;
    }
    const __nv_bfloat16* b_src[2]; uint32_t b_dst[2];
#pragma unroll
    for (int j = 0; j < 2; ++j) {
        int c = tid + j * 256;
        int mat = c >> 8, cc = c & 255, row = cc >> 3, nc = cc & 7;
        b_src[j] = (mat ? Bl : Bh) + (size_t)row * Nw + n0 + nc * 8;
        b_dst[j] = sm + SM_BH_OFF + mat * (SM_BL_OFF - SM_BH_OFF) + row * B_ROW_B + nc * 16;
    }

    float acc[2][4][4];
#pragma unroll
    for (int mt = 0; mt < 2; ++mt)
#pragma unroll
        for (int nt = 0; nt < 4; ++nt)
#pragma unroll
            for (int e = 0; e < 4; ++e) acc[mt][nt][e] = 0.0f;

    auto prefetch = [&](int s, int buf) {
        uint32_t bo = buf * SM_STAGE;
#pragma unroll
        for (int i = 0; i < 4; ++i) cp_async16(a_dst[i] + bo, a_src[i] + s * 32);
#pragma unroll
        for (int j = 0; j < 2; ++j) cp_async16(b_dst[j] + bo, b_src[j] + (size_t)s * 32 * Nw);
        cp_commit();
    };

    prefetch(0, 0);
    for (int s = 0; s < 8; ++s) {
        int buf = s & 1;
        if (s < 7) { prefetch(s + 1, buf ^ 1); cp_wait<1>(); }
        else       { cp_wait<0>(); }
        __syncthreads();

        uint32_t base = sm + buf * SM_STAGE;
#pragma unroll
        for (int k16 = 0; k16 < 2; ++k16) {
            const int kk = k16 * 16;
            uint32_t ah[2][4], al[2][4];
            const int rA = lane & 15, cA = kk + ((lane >> 4) << 3);
#pragma unroll
            for (int mt = 0; mt < 2; ++mt) {
                uint32_t ad = base + (warp_m * 32 + mt * 16 + rA) * A_ROW_B + cA * 2;
                ldsm_x4(ah[mt], ad);
                ldsm_x4(al[mt], ad + SM_AL_OFF);
            }
            uint32_t bh[4][2], bl[4][2];
            const int rB = kk + (lane & 15);
#pragma unroll
            for (int nt = 0; nt < 4; ++nt) {
                uint32_t bd = base + SM_BH_OFF + rB * B_ROW_B + (warp_n * 32 + nt * 8) * 2;
                ldsm_x2t(bh[nt], bd);
                ldsm_x2t(bl[nt], bd + (SM_BL_OFF - SM_BH_OFF));
            }
#pragma unroll
            for (int mt = 0; mt < 2; ++mt)
#pragma unroll
                for (int nt = 0; nt < 4; ++nt) {
                    mma_bf16(acc[mt][nt], ah[mt], bh[nt]);
                    mma_bf16(acc[mt][nt], al[mt], bh[nt]);
                    mma_bf16(acc[mt][nt], ah[mt], bl[nt]);
                }
        }
        __syncthreads();
    }

    // epilogue: fp32 + bias, float2 stores
    const int rbase = m0 + warp_m * 32 + (lane >> 2);
    const int cbase = n0 + warp_n * 32 + (lane & 3) * 2;
#pragma unroll
    for (int mt = 0; mt < 2; ++mt) {
#pragma unroll
        for (int nt = 0; nt < 4; ++nt) {
            int col = cbase + nt * 8;
            float b0 = bias[col], b1 = bias[col + 1];
            float2 v0 = make_float2(acc[mt][nt][0] + b0, acc[mt][nt][1] + b1);
            float2 v1 = make_float2(acc[mt][nt][2] + b0, acc[mt][nt][3] + b1);
            *reinterpret_cast<float2*>(C + (size_t)(rbase + mt * 16) * Nw + col) = v0;
            *reinterpret_cast<float2*>(C + (size_t)(rbase + mt * 16 + 8) * Nw + col) = v1;
        }
    }
}

__global__ __launch_bounds__(256, 2) void gemm1_kernel()
{
    mma_gemm_body(g_xh, g_xl, g_w1h, g_w1l, g_bcat, g_y, NCAT);
}

__global__ __launch_bounds__(256, 2) void gemm2_kernel(const float* __restrict__ proj_b,
                                                       float* __restrict__ out)
{
    mma_gemm_body(g_midh, g_midl, g_w2h, g_w2l, proj_b, out, DD);
}

// ---------------- deformable sampling (warp per (b,n,h)) --------------------
__global__ __launch_bounds__(256) void sample_kernel()
{
    int gw = (blockIdx.x * blockDim.x + threadIdx.x) >> 5;
    int lane = threadIdx.x & 31;

    int h = gw & 7;
    int n = (gw >> 3) & (NN - 1);
    int b = gw >> 15;

    const float* yrow = g_y + (size_t)(b * NN + n) * NCAT;

    float offr[8];
#pragma unroll
    for (int t = 0; t < 8; ++t) offr[t] = yrow[256 + h * 8 + t];
    float aw[4];
#pragma unroll
    for (int p = 0; p < NP; ++p) aw[p] = yrow[320 + h * 4 + p];

    float mx = fmaxf(fmaxf(aw[0], aw[1]), fmaxf(aw[2], aw[3]));
    float s = 0.0f;
#pragma unroll
    for (int p = 0; p < NP; ++p) { aw[p] = __expf(aw[p] - mx); s += aw[p]; }
    float inv = 1.0f / s;

    float px = (float)(n & 63);
    float py = (float)(n >> 6);

    const float* vbase = g_y + (size_t)b * NN * NCAT + h * HD + lane;

    float acc = 0.0f;
#pragma unroll
    for (int p = 0; p < NP; ++p) {
        float gx = px + 2.0f * tanhf(offr[2 * p]);
        float gy = py + 2.0f * tanhf(offr[2 * p + 1]);
        float x0f = floorf(gx), y0f = floorf(gy);
        int x0 = (int)x0f, y0 = (int)y0f;
        int x1 = x0 + 1, y1 = y0 + 1;
        float wx1 = gx - x0f, wy1 = gy - y0f;
        float wx0 = 1.0f - wx1, wy0 = 1.0f - wy1;
        float ap = aw[p] * inv;

        float c00 = ap * wx0 * wy0;
        float c10 = ap * wx1 * wy0;
        float c01 = ap * wx0 * wy1;
        float c11 = ap * wx1 * wy1;

        if (x0 >= 0 && x0 < 64 && y0 >= 0 && y0 < 64)
            acc += c00 * vbase[(size_t)(y0 * 64 + x0) * NCAT];
        if (x1 >= 0 && x1 < 64 && y0 >= 0 && y0 < 64)
            acc += c10 * vbase[(size_t)(y0 * 64 + x1) * NCAT];
        if (x0 >= 0 && x0 < 64 && y1 >= 0 && y1 < 64)
            acc += c01 * vbase[(size_t)(y1 * 64 + x0) * NCAT];
        if (x1 >= 0 && x1 < 64 && y1 >= 0 && y1 < 64)
            acc += c11 * vbase[(size_t)(y1 * 64 + x1) * NCAT];
    }

    size_t ofs = (size_t)(b * NN + n) * DD + h * HD + lane;
    __nv_bfloat16 hh, ll; split_bf16(acc, hh, ll);
    g_midh[ofs] = hh;
    g_midl[ofs] = ll;
}

// ---------------- launch ----------------
extern "C" void kernel_launch(void* const* d_in, const int* in_sizes, int n_in,
                              void* d_out, int out_size)
{
    const float* x      = (const float*)d_in[0];
    const float* qkv_w  = (const float*)d_in[1];
    const float* qkv_b  = (const float*)d_in[2];
    const float* off_w  = (const float*)d_in[3];
    const float* off_b  = (const float*)d_in[4];
    const float* attw_w = (const float*)d_in[5];
    const float* attw_b = (const float*)d_in[6];
    const float* proj_w = (const float*)d_in[7];
    const float* proj_b = (const float*)d_in[8];
    float* out = (float*)d_out;

    cudaFuncSetAttribute(gemm1_kernel, cudaFuncAttributeMaxDynamicSharedMemorySize, SMEM_GEMM_SZ);
    cudaFuncSetAttribute(gemm2_kernel, cudaFuncAttributeMaxDynamicSharedMemorySize, SMEM_GEMM_SZ);

    // 1) split inputs/weights into bf16 hi/lo
    pack_x_kernel<<<(MM * DD + 255) / 256, 256>>>(x);
    pack_w1_kernel<<<(DD * NCAT + 255) / 256, 256>>>(qkv_w, qkv_b, off_w, off_b, attw_w, attw_b);
    pack_w2_kernel<<<(DD * DD + 255) / 256, 256>>>(proj_w);

    // 2) stage-1 GEMM (mma.sync bf16x3): X[32768,256] @ Wcat[256,384] -> g_y
    gemm1_kernel<<<dim3(NCAT / 64, MM / 128), 256, SMEM_GEMM_SZ>>>();

    // 3) deformable bilinear sampling + softmax-weighted accumulation -> bf16 hi/lo
    sample_kernel<<<(BB * NN * NH) / 8, 256>>>();

    // 4) output projection (mma.sync bf16x3): mid @ proj_w[256,256] + b -> out
    gemm2_kernel<<<dim3(DD / 64, MM / 128), 256, SMEM_GEMM_SZ>>>(proj_b, out);
}

// round 4
// speedup vs baseline: 1.7118x; 1.1570x over previous
#include <cuda_runtime.h>
#include <cuda_bf16.h>
#include <cstdint>
#include <math.h>

// Problem constants (fixed shapes from setup_inputs)
#define BB   8
#define NN   4096      // 64*64
#define DD   256
#define NH   8
#define NP   4
#define HD   32
#define MM   (BB*NN)   // 32768 rows
#define NCAT 384       // 256 (v) + 64 (off) + 32 (attw) + 32 pad

// ---------------- scratch (device globals; no allocations allowed) ----------
__device__ float g_y[(size_t)MM * NCAT];          // stage-1 output: v | off | attw
__device__ float g_bcat[NCAT];                    // packed stage-1 bias
__device__ __nv_bfloat16 g_xh[(size_t)MM * DD];   // x split hi
__device__ __nv_bfloat16 g_xl[(size_t)MM * DD];   // x split lo
__device__ __nv_bfloat16 g_midh[(size_t)MM * DD]; // sampled output split hi
__device__ __nv_bfloat16 g_midl[(size_t)MM * DD]; // sampled output split lo
__device__ __nv_bfloat16 g_w1h[DD * NCAT];        // [k][n] stage-1 weights hi
__device__ __nv_bfloat16 g_w1l[DD * NCAT];
__device__ __nv_bfloat16 g_w2h[DD * DD];          // [k][n] proj weights hi
__device__ __nv_bfloat16 g_w2l[DD * DD];

// =================== helpers ===================
__device__ __forceinline__ uint32_t smem_to_u32(const void* p) {
    uint32_t a;
    asm("{ .reg .u64 t; cvta.to.shared.u64 t, %1; cvt.u32.u64 %0, t; }" : "=r"(a) : "l"(p));
    return a;
}
__device__ __forceinline__ void split_bf16(float w, __nv_bfloat16& h, __nv_bfloat16& l) {
    h = __float2bfloat16_rn(w);
    l = __float2bfloat16_rn(w - __bfloat162float(h));
}
__device__ __forceinline__ void cp_async16(uint32_t dst, const void* src) {
    asm volatile("{ .reg .u64 g; cvta.to.global.u64 g, %1; cp.async.cg.shared.global [%0], [g], 16; }"
                 :: "r"(dst), "l"(src));
}
__device__ __forceinline__ void cp_commit() {
    asm volatile("cp.async.commit_group;");
}
__device__ __forceinline__ void ldsm_x4(uint32_t (&r)[4], uint32_t addr) {
    asm volatile("ldmatrix.sync.aligned.m8n8.x4.shared.b16 {%0,%1,%2,%3}, [%4];"
                 : "=r"(r[0]), "=r"(r[1]), "=r"(r[2]), "=r"(r[3]) : "r"(addr));
}
__device__ __forceinline__ void ldsm_x2t(uint32_t (&r)[2], uint32_t addr) {
    asm volatile("ldmatrix.sync.aligned.m8n8.x2.trans.shared.b16 {%0,%1}, [%2];"
                 : "=r"(r[0]), "=r"(r[1]) : "r"(addr));
}
__device__ __forceinline__ void mma_bf16(float (&c)[4], const uint32_t (&a)[4], const uint32_t (&b)[2]) {
    asm volatile("mma.sync.aligned.m16n8k16.row.col.f32.bf16.bf16.f32 "
                 "{%0,%1,%2,%3}, {%4,%5,%6,%7}, {%8,%9}, {%0,%1,%2,%3};"
                 : "+f"(c[0]), "+f"(c[1]), "+f"(c[2]), "+f"(c[3])
                 : "r"(a[0]), "r"(a[1]), "r"(a[2]), "r"(a[3]), "r"(b[0]), "r"(b[1]));
}

// =================== pack kernels ===================
__global__ void pack_x_kernel(const float* __restrict__ x)
{
    int idx = blockIdx.x * blockDim.x + threadIdx.x;   // over MM*DD/4
    if (idx < MM * DD / 4) {
        float4 v = reinterpret_cast<const float4*>(x)[idx];
        __nv_bfloat16 h0, l0, h1, l1, h2, l2, h3, l3;
        split_bf16(v.x, h0, l0); split_bf16(v.y, h1, l1);
        split_bf16(v.z, h2, l2); split_bf16(v.w, h3, l3);
        uint2 ph, pl;
        ph.x = ((uint32_t)__bfloat16_as_ushort(h1) << 16) | __bfloat16_as_ushort(h0);
        ph.y = ((uint32_t)__bfloat16_as_ushort(h3) << 16) | __bfloat16_as_ushort(h2);
        pl.x = ((uint32_t)__bfloat16_as_ushort(l1) << 16) | __bfloat16_as_ushort(l0);
        pl.y = ((uint32_t)__bfloat16_as_ushort(l3) << 16) | __bfloat16_as_ushort(l2);
        reinterpret_cast<uint2*>(g_xh)[idx] = ph;
        reinterpret_cast<uint2*>(g_xl)[idx] = pl;
    }
}

__global__ void pack_w1_kernel(const float* __restrict__ qkv_w, const float* __restrict__ qkv_b,
                               const float* __restrict__ off_w, const float* __restrict__ off_b,
                               const float* __restrict__ attw_w, const float* __restrict__ attw_b)
{
    int idx = blockIdx.x * blockDim.x + threadIdx.x;   // over DD*NCAT, idx = k*384 + n
    if (idx < DD * NCAT) {
        int k = idx / NCAT, n = idx % NCAT;
        float w;
        if (n < 256)      w = qkv_w[k * 768 + 512 + n];
        else if (n < 320) w = off_w[k * 64 + (n - 256)];
        else if (n < 352) w = attw_w[k * 32 + (n - 320)];
        else              w = 0.0f;
        __nv_bfloat16 h, l; split_bf16(w, h, l);
        g_w1h[idx] = h; g_w1l[idx] = l;
    }
    if (idx < NCAT) {
        float bv;
        if (idx < 256)      bv = qkv_b[512 + idx];
        else if (idx < 320) bv = off_b[idx - 256];
        else if (idx < 352) bv = attw_b[idx - 320];
        else                bv = 0.0f;
        g_bcat[idx] = bv;
    }
}

__global__ void pack_w2_kernel(const float* __restrict__ proj_w)
{
    int idx = blockIdx.x * blockDim.x + threadIdx.x;   // proj_w already [k][n]
    if (idx < DD * DD) {
        __nv_bfloat16 h, l; split_bf16(proj_w[idx], h, l);
        g_w2h[idx] = h; g_w2l[idx] = l;
    }
}

// =================== mma.sync bf16x3 GEMM ===================
// C[M, Nw] = A[M,256] @ B[256, Nw] + bias   (A = Ah+Al, B = Bh+Bl bf16 splits)
// CTA tile 128x64, BK=32, 256 threads, warp tile 32x32 (4x2 warp grid).
// 3-stage cp.async pipeline. A rows padded to 80B, B rows to 144B (conflict-free).
#define A_ROW_B   80
#define B_ROW_B   144
#define SM_A_SZ   10240                     // 128*80
#define SM_B_OFF  20480                     // 2 * SM_A_SZ
#define SM_B_SZ   4608                      // 32*144
#define SM_STAGE  29696                     // 20480 + 2*4608
#define SMEM_GEMM_SZ (3 * SM_STAGE)

__device__ __forceinline__ void mma_gemm_body(const __nv_bfloat16* __restrict__ Ah,
                                              const __nv_bfloat16* __restrict__ Al,
                                              const __nv_bfloat16* __restrict__ Bh,
                                              const __nv_bfloat16* __restrict__ Bl,
                                              const float* __restrict__ bias,
                                              float* __restrict__ C, int Nw)
{
    extern __shared__ char smem[];
    const uint32_t sm = smem_to_u32(smem);
    const int tid = threadIdx.x;
    const int lane = tid & 31, wid = tid >> 5;
    const int warp_m = wid >> 1, warp_n = wid & 1;
    const int m0 = blockIdx.y * 128, n0 = blockIdx.x * 64;

    // per-thread cp.async chunk assignments (A: 4 chunks, B: 2 chunks of 16B)
    const __nv_bfloat16* a_src[4]; uint32_t a_dst[4];
#pragma unroll
    for (int i = 0; i < 4; ++i) {
        int c = tid + i * 256;
        int mat = c >> 9, cc = c & 511, row = cc >> 2, kc = cc & 3;
        a_src[i] = (mat ? Al : Ah) + (size_t)(m0 + row) * DD + kc * 8;
        a_dst[i] = sm + mat * SM_A_SZ + row * A_ROW_B + kc * 16;
    }
    const __nv_bfloat16* b_src[2]; uint32_t b_dst[2];
#pragma unroll
    for (int j = 0; j < 2; ++j) {
        int c = tid + j * 256;
        int mat = c >> 8, cc = c & 255, row = cc >> 3, nc = cc & 7;
        b_src[j] = (mat ? Bl : Bh) + (size_t)row * Nw + n0 + nc * 8;
        b_dst[j] = sm + SM_B_OFF + mat * SM_B_SZ + row * B_ROW_B + nc * 16;
    }

    float acc[2][4][4];
#pragma unroll
    for (int mt = 0; mt < 2; ++mt)
#pragma unroll
        for (int nt = 0; nt < 4; ++nt)
#pragma unroll
            for (int e = 0; e < 4; ++e) acc[mt][nt][e] = 0.0f;

    auto prefetch = [&](int s, int buf) {
        uint32_t bo = (uint32_t)buf * SM_STAGE;
#pragma unroll
        for (int i = 0; i < 4; ++i) cp_async16(a_dst[i] + bo, a_src[i] + s * 32);
#pragma unroll
        for (int j = 0; j < 2; ++j) cp_async16(b_dst[j] + bo, b_src[j] + (size_t)s * 32 * Nw);
        cp_commit();
    };

    prefetch(0, 0);
    prefetch(1, 1);
    int buf = 0;
    for (int s = 0; s < 8; ++s) {
        if (s < 7) asm volatile("cp.async.wait_group 1;");
        else       asm volatile("cp.async.wait_group 0;");
        __syncthreads();
        if (s + 2 < 8) prefetch(s + 2, (s + 2) % 3);

        uint32_t base = sm + (uint32_t)buf * SM_STAGE;
#pragma unroll
        for (int k16 = 0; k16 < 2; ++k16) {
            const int kk = k16 * 16;
            uint32_t ah[2][4], al[2][4];
            const int rA = lane & 15, cA = kk + ((lane >> 4) << 3);
#pragma unroll
            for (int mt = 0; mt < 2; ++mt) {
                uint32_t ad = base + (warp_m * 32 + mt * 16 + rA) * A_ROW_B + cA * 2;
                ldsm_x4(ah[mt], ad);
                ldsm_x4(al[mt], ad + SM_A_SZ);
            }
            uint32_t bh[4][2], bl[4][2];
            const int rB = kk + (lane & 15);
#pragma unroll
            for (int nt = 0; nt < 4; ++nt) {
                uint32_t bd = base + SM_B_OFF + rB * B_ROW_B + (warp_n * 32 + nt * 8) * 2;
                ldsm_x2t(bh[nt], bd);
                ldsm_x2t(bl[nt], bd + SM_B_SZ);
            }
#pragma unroll
            for (int mt = 0; mt < 2; ++mt)
#pragma unroll
                for (int nt = 0; nt < 4; ++nt) {
                    mma_bf16(acc[mt][nt], ah[mt], bh[nt]);
                    mma_bf16(acc[mt][nt], al[mt], bh[nt]);
                    mma_bf16(acc[mt][nt], ah[mt], bl[nt]);
                }
        }
        __syncthreads();
        buf = (buf + 1) % 3;
    }

    // epilogue: fp32 + bias, float2 stores
    const int rbase = m0 + warp_m * 32 + (lane >> 2);
    const int cbase = n0 + warp_n * 32 + (lane & 3) * 2;
#pragma unroll
    for (int mt = 0; mt < 2; ++mt) {
#pragma unroll
        for (int nt = 0; nt < 4; ++nt) {
            int col = cbase + nt * 8;
            float b0 = bias[col], b1 = bias[col + 1];
            float2 v0 = make_float2(acc[mt][nt][0] + b0, acc[mt][nt][1] + b1);
            float2 v1 = make_float2(acc[mt][nt][2] + b0, acc[mt][nt][3] + b1);
            *reinterpret_cast<float2*>(C + (size_t)(rbase + mt * 16) * Nw + col) = v0;
            *reinterpret_cast<float2*>(C + (size_t)(rbase + mt * 16 + 8) * Nw + col) = v1;
        }
    }
}

__global__ __launch_bounds__(256, 2) void gemm1_kernel()
{
    mma_gemm_body(g_xh, g_xl, g_w1h, g_w1l, g_bcat, g_y, NCAT);
}

__global__ __launch_bounds__(256, 2) void gemm2_kernel(const float* __restrict__ proj_b,
                                                       float* __restrict__ out)
{
    mma_gemm_body(g_midh, g_midl, g_w2h, g_w2l, proj_b, out, DD);
}

// ---------------- deformable sampling: smem-tiled ---------------------------
// One block per (b, h, 16x16 pixel tile). Offsets are 2*tanh in (-2,2), so all
// bilinear corners live in a 20x20 window [tx0-2, tx0+17] x [ty0-2, ty0+17].
// Stage window (fp32, zero-filled OOB) in smem: gathers become conflict-free
// LDS (lane = channel -> 32 distinct banks). OOB corners contribute 0 exactly
// like the reference's zero-weight path.
#define TILE_PX  16
#define WIN      20                         // 16 + 2*2 halo
#define SMEM_SAMP_SZ (WIN * WIN * HD * 4)   // 51200 bytes

__global__ __launch_bounds__(256) void sample_kernel()
{
    extern __shared__ float vt[];           // [WIN*WIN][32]
    const int tid = threadIdx.x;
    const int lane = tid & 31, wid = tid >> 5;

    const int t = blockIdx.x;
    const int tile = t & 15;
    const int h = (t >> 4) & 7;
    const int b = t >> 7;
    const int tx0 = (tile & 3) * TILE_PX;
    const int ty0 = (tile >> 2) * TILE_PX;

    // ---- load 20x20x32 window (zero-filled at image borders) ----
    for (int p = wid; p < WIN * WIN; p += 8) {
        int py = p / WIN, px = p % WIN;
        int gy = ty0 - 2 + py, gx = tx0 - 2 + px;
        float v = 0.0f;
        if (gy >= 0 && gy < 64 && gx >= 0 && gx < 64)
            v = g_y[(size_t)(b * NN + gy * 64 + gx) * NCAT + h * HD + lane];
        vt[p * HD + lane] = v;
    }
    __syncthreads();

    // ---- compute: warp per pixel, 32 pixels per warp ----
    for (int q = wid; q < TILE_PX * TILE_PX; q += 8) {
        int py = q >> 4, px = q & 15;
        int n = (ty0 + py) * 64 + (tx0 + px);
        const float* yrow = g_y + (size_t)(b * NN + n) * NCAT;

        float offr[8];
#pragma unroll
        for (int i = 0; i < 8; ++i) offr[i] = yrow[256 + h * 8 + i];
        float aw[4];
#pragma unroll
        for (int p = 0; p < NP; ++p) aw[p] = yrow[320 + h * 4 + p];

        float mx = fmaxf(fmaxf(aw[0], aw[1]), fmaxf(aw[2], aw[3]));
        float s = 0.0f;
#pragma unroll
        for (int p = 0; p < NP; ++p) { aw[p] = __expf(aw[p] - mx); s += aw[p]; }
        float inv = 1.0f / s;

        float acc = 0.0f;
#pragma unroll
        for (int p = 0; p < NP; ++p) {
            // local window coords: global - (tx0-2); halo guarantees [0,19]
            float lgx = (float)(px + 2) + 2.0f * tanhf(offr[2 * p]);
            float lgy = (float)(py + 2) + 2.0f * tanhf(offr[2 * p + 1]);
            float x0f = floorf(lgx), y0f = floorf(lgy);
            int x0 = (int)x0f, y0 = (int)y0f;
            float wx1 = lgx - x0f, wy1 = lgy - y0f;
            float wx0 = 1.0f - wx1, wy0 = 1.0f - wy1;
            float ap = aw[p] * inv;

            const float* c00 = vt + (y0 * WIN + x0) * HD + lane;
            float v00 = c00[0];
            float v10 = c00[HD];
            float v01 = c00[WIN * HD];
            float v11 = c00[WIN * HD + HD];
            acc += ap * (wy0 * (wx0 * v00 + wx1 * v10) + wy1 * (wx0 * v01 + wx1 * v11));
        }

        size_t ofs = (size_t)(b * NN + n) * DD + h * HD + lane;
        __nv_bfloat16 hh, ll; split_bf16(acc, hh, ll);
        g_midh[ofs] = hh;
        g_midl[ofs] = ll;
    }
}

// ---------------- launch ----------------
extern "C" void kernel_launch(void* const* d_in, const int* in_sizes, int n_in,
                              void* d_out, int out_size)
{
    const float* x      = (const float*)d_in[0];
    const float* qkv_w  = (const float*)d_in[1];
    const float* qkv_b  = (const float*)d_in[2];
    const float* off_w  = (const float*)d_in[3];
    const float* off_b  = (const float*)d_in[4];
    const float* attw_w = (const float*)d_in[5];
    const float* attw_b = (const float*)d_in[6];
    const float* proj_w = (const float*)d_in[7];
    const float* proj_b = (const float*)d_in[8];
    float* out = (float*)d_out;

    cudaFuncSetAttribute(gemm1_kernel, cudaFuncAttributeMaxDynamicSharedMemorySize, SMEM_GEMM_SZ);
    cudaFuncSetAttribute(gemm2_kernel, cudaFuncAttributeMaxDynamicSharedMemorySize, SMEM_GEMM_SZ);
    cudaFuncSetAttribute(sample_kernel, cudaFuncAttributeMaxDynamicSharedMemorySize, SMEM_SAMP_SZ);

    // 1) split inputs/weights into bf16 hi/lo
    pack_x_kernel<<<(MM * DD / 4 + 255) / 256, 256>>>(x);
    pack_w1_kernel<<<(DD * NCAT + 255) / 256, 256>>>(qkv_w, qkv_b, off_w, off_b, attw_w, attw_b);
    pack_w2_kernel<<<(DD * DD + 255) / 256, 256>>>(proj_w);

    // 2) stage-1 GEMM (mma.sync bf16x3): X[32768,256] @ Wcat[256,384] -> g_y
    gemm1_kernel<<<dim3(NCAT / 64, MM / 128), 256, SMEM_GEMM_SZ>>>();

    // 3) deformable sampling, smem-tiled: (b, h, 16x16 tile) per block
    sample_kernel<<<BB * NH * 16, 256, SMEM_SAMP_SZ>>>();

    // 4) output projection (mma.sync bf16x3): mid @ proj_w[256,256] + b -> out
    gemm2_kernel<<<dim3(DD / 64, MM / 128), 256, SMEM_GEMM_SZ>>>(proj_b, out);
}

// round 6
// speedup vs baseline: 1.7203x; 1.0050x over previous
#include <cuda_runtime.h>
#include <cuda_bf16.h>
#include <cstdint>
#include <math.h>

// Problem constants (fixed shapes from setup_inputs)
#define BB   8
#define NN   4096      // 64*64
#define DD   256
#define NH   8
#define NP   4
#define HD   32
#define MM   (BB*NN)   // 32768 rows
#define NCAT 384       // 256 (v) + 64 (off) + 32 (attw) + 32 pad

// ---------------- scratch (device globals; no allocations allowed) ----------
__device__ float g_y[(size_t)MM * NCAT];          // stage-1 output: v | off | attw
__device__ float g_bcat[NCAT];                    // packed stage-1 bias
__device__ __nv_bfloat16 g_xh[(size_t)MM * DD];   // x split hi
__device__ __nv_bfloat16 g_xl[(size_t)MM * DD];   // x split lo
__device__ __nv_bfloat16 g_midh[(size_t)MM * DD]; // sampled output split hi
__device__ __nv_bfloat16 g_midl[(size_t)MM * DD]; // sampled output split lo
__device__ __nv_bfloat16 g_w1h[DD * NCAT];        // [k][n] stage-1 weights hi
__device__ __nv_bfloat16 g_w1l[DD * NCAT];
__device__ __nv_bfloat16 g_w2h[DD * DD];          // [k][n] proj weights hi
__device__ __nv_bfloat16 g_w2l[DD * DD];

// =================== helpers ===================
__device__ __forceinline__ uint32_t smem_to_u32(const void* p) {
    uint32_t a;
    asm("{ .reg .u64 t; cvta.to.shared.u64 t, %1; cvt.u32.u64 %0, t; }" : "=r"(a) : "l"(p));
    return a;
}
__device__ __forceinline__ void split_bf16(float w, __nv_bfloat16& h, __nv_bfloat16& l) {
    h = __float2bfloat16_rn(w);
    l = __float2bfloat16_rn(w - __bfloat162float(h));
}
__device__ __forceinline__ void cp_async16(uint32_t dst, const void* src) {
    asm volatile("{ .reg .u64 g; cvta.to.global.u64 g, %1; cp.async.cg.shared.global [%0], [g], 16; }"
                 :: "r"(dst), "l"(src));
}
__device__ __forceinline__ void cp_commit() {
    asm volatile("cp.async.commit_group;");
}
__device__ __forceinline__ void ldsm_x4(uint32_t (&r)[4], uint32_t addr) {
    asm volatile("ldmatrix.sync.aligned.m8n8.x4.shared.b16 {%0,%1,%2,%3}, [%4];"
                 : "=r"(r[0]), "=r"(r[1]), "=r"(r[2]), "=r"(r[3]) : "r"(addr));
}
__device__ __forceinline__ void ldsm_x2t(uint32_t (&r)[2], uint32_t addr) {
    asm volatile("ldmatrix.sync.aligned.m8n8.x2.trans.shared.b16 {%0,%1}, [%2];"
                 : "=r"(r[0]), "=r"(r[1]) : "r"(addr));
}
__device__ __forceinline__ void mma_bf16(float (&c)[4], const uint32_t (&a)[4], const uint32_t (&b)[2]) {
    asm volatile("mma.sync.aligned.m16n8k16.row.col.f32.bf16.bf16.f32 "
                 "{%0,%1,%2,%3}, {%4,%5,%6,%7}, {%8,%9}, {%0,%1,%2,%3};"
                 : "+f"(c[0]), "+f"(c[1]), "+f"(c[2]), "+f"(c[3])
                 : "r"(a[0]), "r"(a[1]), "r"(a[2]), "r"(a[3]), "r"(b[0]), "r"(b[1]));
}

// =================== pack kernels ===================
__global__ void pack_x_kernel(const float* __restrict__ x)
{
    int idx = blockIdx.x * blockDim.x + threadIdx.x;   // over MM*DD/4
    if (idx < MM * DD / 4) {
        float4 v = reinterpret_cast<const float4*>(x)[idx];
        __nv_bfloat16 h0, l0, h1, l1, h2, l2, h3, l3;
        split_bf16(v.x, h0, l0); split_bf16(v.y, h1, l1);
        split_bf16(v.z, h2, l2); split_bf16(v.w, h3, l3);
        uint2 ph, pl;
        ph.x = ((uint32_t)__bfloat16_as_ushort(h1) << 16) | __bfloat16_as_ushort(h0);
        ph.y = ((uint32_t)__bfloat16_as_ushort(h3) << 16) | __bfloat16_as_ushort(h2);
        pl.x = ((uint32_t)__bfloat16_as_ushort(l1) << 16) | __bfloat16_as_ushort(l0);
        pl.y = ((uint32_t)__bfloat16_as_ushort(l3) << 16) | __bfloat16_as_ushort(l2);
        reinterpret_cast<uint2*>(g_xh)[idx] = ph;
        reinterpret_cast<uint2*>(g_xl)[idx] = pl;
    }
}

// fused: stage-1 weight concat/split + bias + proj weight split
__global__ void pack_w_kernel(const float* __restrict__ qkv_w, const float* __restrict__ qkv_b,
                              const float* __restrict__ off_w, const float* __restrict__ off_b,
                              const float* __restrict__ attw_w, const float* __restrict__ attw_b,
                              const float* __restrict__ proj_w)
{
    int idx = blockIdx.x * blockDim.x + threadIdx.x;
    if (idx < DD * NCAT) {
        int k = idx / NCAT, n = idx % NCAT;
        float w;
        if (n < 256)      w = qkv_w[k * 768 + 512 + n];
        else if (n < 320) w = off_w[k * 64 + (n - 256)];
        else if (n < 352) w = attw_w[k * 32 + (n - 320)];
        else              w = 0.0f;
        __nv_bfloat16 h, l; split_bf16(w, h, l);
        g_w1h[idx] = h; g_w1l[idx] = l;
    }
    int idx2 = idx - DD * NCAT;
    if (idx2 >= 0 && idx2 < DD * DD) {
        __nv_bfloat16 h, l; split_bf16(proj_w[idx2], h, l);
        g_w2h[idx2] = h; g_w2l[idx2] = l;
    }
    if (idx < NCAT) {
        float bv;
        if (idx < 256)      bv = qkv_b[512 + idx];
        else if (idx < 320) bv = off_b[idx - 256];
        else if (idx < 352) bv = attw_b[idx - 320];
        else                bv = 0.0f;
        g_bcat[idx] = bv;
    }
}

// =================== mma.sync bf16x3 GEMM ===================
// C[M, Nw] = A[M,256] @ B[256, Nw] + bias   (A = Ah+Al, B = Bh+Bl bf16 splits)
// CTA tile 128x64, BK=32, 256 threads, warp tile 32x32 (4x2 warp grid).
// 3-stage cp.async pipeline, ONE barrier per stage.
// A rows padded to 80B (16B multiple — cp.async requires 16B-aligned dst),
// B rows to 144B; both bank-conflict-free for ldmatrix.
#define A_ROW_B   80
#define B_ROW_B   144
#define SM_A_SZ   10240                     // 128*80
#define SM_B_OFF  20480                     // 2 * SM_A_SZ
#define SM_B_SZ   4608                      // 32*144
#define SM_STAGE  29696                     // 20480 + 2*4608
#define N_STAGE   3
#define SMEM_GEMM_SZ (N_STAGE * SM_STAGE)   // 89088

__device__ __forceinline__ void mma_gemm_body(const __nv_bfloat16* __restrict__ Ah,
                                              const __nv_bfloat16* __restrict__ Al,
                                              const __nv_bfloat16* __restrict__ Bh,
                                              const __nv_bfloat16* __restrict__ Bl,
                                              const float* __restrict__ bias,
                                              float* __restrict__ C, int Nw)
{
    extern __shared__ char smem[];
    const uint32_t sm = smem_to_u32(smem);
    const int tid = threadIdx.x;
    const int lane = tid & 31, wid = tid >> 5;
    const int warp_m = wid >> 1, warp_n = wid & 1;
    const int m0 = blockIdx.y * 128, n0 = blockIdx.x * 64;

    // per-thread cp.async chunk assignments (A: 4 chunks, B: 2 chunks of 16B)
    const __nv_bfloat16* a_src[4]; uint32_t a_dst[4];
#pragma unroll
    for (int i = 0; i < 4; ++i) {
        int c = tid + i * 256;
        int mat = c >> 9, cc = c & 511, row = cc >> 2, kc = cc & 3;
        a_src[i] = (mat ? Al : Ah) + (size_t)(m0 + row) * DD + kc * 8;
        a_dst[i] = sm + mat * SM_A_SZ + row * A_ROW_B + kc * 16;
    }
    const __nv_bfloat16* b_src[2]; uint32_t b_dst[2];
#pragma unroll
    for (int j = 0; j < 2; ++j) {
        int c = tid + j * 256;
        int mat = c >> 8, cc = c & 255, row = cc >> 3, nc = cc & 7;
        b_src[j] = (mat ? Bl : Bh) + (size_t)row * Nw + n0 + nc * 8;
        b_dst[j] = sm + SM_B_OFF + mat * SM_B_SZ + row * B_ROW_B + nc * 16;
    }

    float acc[2][4][4];
#pragma unroll
    for (int mt = 0; mt < 2; ++mt)
#pragma unroll
        for (int nt = 0; nt < 4; ++nt)
#pragma unroll
            for (int e = 0; e < 4; ++e) acc[mt][nt][e] = 0.0f;

    auto prefetch = [&](int s, int buf) {
        uint32_t bo = (uint32_t)buf * SM_STAGE;
#pragma unroll
        for (int i = 0; i < 4; ++i) cp_async16(a_dst[i] + bo, a_src[i] + s * 32);
#pragma unroll
        for (int j = 0; j < 2; ++j) cp_async16(b_dst[j] + bo, b_src[j] + (size_t)s * 32 * Nw);
        cp_commit();
    };

    prefetch(0, 0);
    prefetch(1, 1);
    int buf = 0;
    for (int s = 0; s < 8; ++s) {
        if (s < 7) asm volatile("cp.async.wait_group 1;");
        else       asm volatile("cp.async.wait_group 0;");
        __syncthreads();
        // This barrier proves all warps finished computing stage s-1, so
        // buffer (s+2)%3 == (s-1)%3 is reusable — no trailing barrier needed.
        if (s + 2 < 8) prefetch(s + 2, (s + 2) % 3);

        uint32_t base = sm + (uint32_t)buf * SM_STAGE;
#pragma unroll
        for (int k16 = 0; k16 < 2; ++k16) {
            const int kk = k16 * 16;
            uint32_t ah[2][4], al[2][4];
            const int rA = lane & 15, cA = kk + ((lane >> 4) << 3);
#pragma unroll
            for (int mt = 0; mt < 2; ++mt) {
                uint32_t ad = base + (warp_m * 32 + mt * 16 + rA) * A_ROW_B + cA * 2;
                ldsm_x4(ah[mt], ad);
                ldsm_x4(al[mt], ad + SM_A_SZ);
            }
            uint32_t bh[4][2], bl[4][2];
            const int rB = kk + (lane & 15);
#pragma unroll
            for (int nt = 0; nt < 4; ++nt) {
                uint32_t bd = base + SM_B_OFF + rB * B_ROW_B + (warp_n * 32 + nt * 8) * 2;
                ldsm_x2t(bh[nt], bd);
                ldsm_x2t(bl[nt], bd + SM_B_SZ);
            }
#pragma unroll
            for (int mt = 0; mt < 2; ++mt)
#pragma unroll
                for (int nt = 0; nt < 4; ++nt) {
                    mma_bf16(acc[mt][nt], ah[mt], bh[nt]);
                    mma_bf16(acc[mt][nt], al[mt], bh[nt]);
                    mma_bf16(acc[mt][nt], ah[mt], bl[nt]);
                }
        }
        buf = (buf + 1) % 3;
    }

    // epilogue: fp32 + bias, float2 stores
    const int rbase = m0 + warp_m * 32 + (lane >> 2);
    const int cbase = n0 + warp_n * 32 + (lane & 3) * 2;
#pragma unroll
    for (int mt = 0; mt < 2; ++mt) {
#pragma unroll
        for (int nt = 0; nt < 4; ++nt) {
            int col = cbase + nt * 8;
            float b0 = bias[col], b1 = bias[col + 1];
            float2 v0 = make_float2(acc[mt][nt][0] + b0, acc[mt][nt][1] + b1);
            float2 v1 = make_float2(acc[mt][nt][2] + b0, acc[mt][nt][3] + b1);
            *reinterpret_cast<float2*>(C + (size_t)(rbase + mt * 16) * Nw + col) = v0;
            *reinterpret_cast<float2*>(C + (size_t)(rbase + mt * 16 + 8) * Nw + col) = v1;
        }
    }
}

__global__ __launch_bounds__(256, 2) void gemm1_kernel()
{
    mma_gemm_body(g_xh, g_xl, g_w1h, g_w1l, g_bcat, g_y, NCAT);
}

__global__ __launch_bounds__(256, 2) void gemm2_kernel(const float* __restrict__ proj_b,
                                                       float* __restrict__ out)
{
    mma_gemm_body(g_midh, g_midl, g_w2h, g_w2l, proj_b, out, DD);
}

// ---------------- deformable sampling: smem-tiled ---------------------------
// One block per (b, h, 16x16 pixel tile). Offsets are 2*tanh in (-2,2), so all
// bilinear corners live in a 20x20 window. Stage window (fp32, zero-filled OOB)
// in smem: gathers become conflict-free LDS (lane = channel).
#define TILE_PX  16
#define WIN      20                         // 16 + 2*2 halo
#define SMEM_SAMP_SZ (WIN * WIN * HD * 4)   // 51200 bytes

__global__ __launch_bounds__(256) void sample_kernel()
{
    extern __shared__ float vt[];           // [WIN*WIN][32]
    const int tid = threadIdx.x;
    const int lane = tid & 31, wid = tid >> 5;

    const int t = blockIdx.x;
    const int tile = t & 15;
    const int h = (t >> 4) & 7;
    const int b = t >> 7;
    const int tx0 = (tile & 3) * TILE_PX;
    const int ty0 = (tile >> 2) * TILE_PX;

    // ---- load 20x20x32 window (zero-filled at image borders) ----
    for (int p = wid; p < WIN * WIN; p += 8) {
        int py = p / WIN, px = p % WIN;
        int gy = ty0 - 2 + py, gx = tx0 - 2 + px;
        float v = 0.0f;
        if (gy >= 0 && gy < 64 && gx >= 0 && gx < 64)
            v = g_y[(size_t)(b * NN + gy * 64 + gx) * NCAT + h * HD + lane];
        vt[p * HD + lane] = v;
    }
    __syncthreads();

    // ---- compute: warp per pixel, 32 pixels per warp ----
    for (int q = wid; q < TILE_PX * TILE_PX; q += 8) {
        int py = q >> 4, px = q & 15;
        int n = (ty0 + py) * 64 + (tx0 + px);
        const float* yrow = g_y + (size_t)(b * NN + n) * NCAT;

        float offr[8];
#pragma unroll
        for (int i = 0; i < 8; ++i) offr[i] = yrow[256 + h * 8 + i];
        float aw[4];
#pragma unroll
        for (int p = 0; p < NP; ++p) aw[p] = yrow[320 + h * 4 + p];

        float mx = fmaxf(fmaxf(aw[0], aw[1]), fmaxf(aw[2], aw[3]));
        float s = 0.0f;
#pragma unroll
        for (int p = 0; p < NP; ++p) { aw[p] = __expf(aw[p] - mx); s += aw[p]; }
        float inv = 1.0f / s;

        float acc = 0.0f;
#pragma unroll
        for (int p = 0; p < NP; ++p) {
            float lgx = (float)(px + 2) + 2.0f * tanhf(offr[2 * p]);
            float lgy = (float)(py + 2) + 2.0f * tanhf(offr[2 * p + 1]);
            float x0f = floorf(lgx), y0f = floorf(lgy);
            int x0 = (int)x0f, y0 = (int)y0f;
            float wx1 = lgx - x0f, wy1 = lgy - y0f;
            float wx0 = 1.0f - wx1, wy0 = 1.0f - wy1;
            float ap = aw[p] * inv;

            const float* c00 = vt + (y0 * WIN + x0) * HD + lane;
            float v00 = c00[0];
            float v10 = c00[HD];
            float v01 = c00[WIN * HD];
            float v11 = c00[WIN * HD + HD];
            acc += ap * (wy0 * (wx0 * v00 + wx1 * v10) + wy1 * (wx0 * v01 + wx1 * v11));
        }

        size_t ofs = (size_t)(b * NN + n) * DD + h * HD + lane;
        __nv_bfloat16 hh, ll; split_bf16(acc, hh, ll);
        g_midh[ofs] = hh;
        g_midl[ofs] = ll;
    }
}

// ---------------- launch ----------------
extern "C" void kernel_launch(void* const* d_in, const int* in_sizes, int n_in,
                              void* d_out, int out_size)
{
    const float* x      = (const float*)d_in[0];
    const float* qkv_w  = (const float*)d_in[1];
    const float* qkv_b  = (const float*)d_in[2];
    const float* off_w  = (const float*)d_in[3];
    const float* off_b  = (const float*)d_in[4];
    const float* attw_w = (const float*)d_in[5];
    const float* attw_b = (const float*)d_in[6];
    const float* proj_w = (const float*)d_in[7];
    const float* proj_b = (const float*)d_in[8];
    float* out = (float*)d_out;

    cudaFuncSetAttribute(gemm1_kernel, cudaFuncAttributeMaxDynamicSharedMemorySize, SMEM_GEMM_SZ);
    cudaFuncSetAttribute(gemm2_kernel, cudaFuncAttributeMaxDynamicSharedMemorySize, SMEM_GEMM_SZ);
    cudaFuncSetAttribute(sample_kernel, cudaFuncAttributeMaxDynamicSharedMemorySize, SMEM_SAMP_SZ);

    // 1) split inputs/weights into bf16 hi/lo
    pack_x_kernel<<<(MM * DD / 4 + 255) / 256, 256>>>(x);
    pack_w_kernel<<<(DD * NCAT + DD * DD + 255) / 256, 256>>>(
        qkv_w, qkv_b, off_w, off_b, attw_w, attw_b, proj_w);

    // 2) stage-1 GEMM (mma.sync bf16x3): X[32768,256] @ Wcat[256,384] -> g_y
    gemm1_kernel<<<dim3(NCAT / 64, MM / 128), 256, SMEM_GEMM_SZ>>>();

    // 3) deformable sampling, smem-tiled: (b, h, 16x16 tile) per block
    sample_kernel<<<BB * NH * 16, 256, SMEM_SAMP_SZ>>>();

    // 4) output projection (mma.sync bf16x3): mid @ proj_w[256,256] + b -> out
    gemm2_kernel<<<dim3(DD / 64, MM / 128), 256, SMEM_GEMM_SZ>>>(proj_b, out);
}

// round 7
// speedup vs baseline: 2.0296x; 1.1798x over previous
#include <cuda_runtime.h>
#include <cuda_bf16.h>
#include <cstdint>
#include <math.h>

// Problem constants (fixed shapes from setup_inputs)
#define BB   8
#define NN   4096      // 64*64
#define DD   256
#define NH   8
#define NP   4
#define HD   32
#define MM   (BB*NN)   // 32768 rows
#define NCAT 384       // 256 (v) + 64 (off) + 32 (attw) + 32 pad

// ---------------- scratch (device globals; no allocations allowed) ----------
__device__ float g_y[(size_t)MM * NCAT];          // stage-1 output: v | off | attw
__device__ float g_bcat[NCAT];                    // packed stage-1 bias
__device__ float g_prep[(size_t)MM * NH * 12];    // per (b,n,h): gx[4],gy[4],ap[4]
__device__ __nv_bfloat16 g_xh[(size_t)MM * DD];   // x split hi
__device__ __nv_bfloat16 g_xl[(size_t)MM * DD];   // x split lo
__device__ __nv_bfloat16 g_midh[(size_t)MM * DD]; // sampled output split hi
__device__ __nv_bfloat16 g_midl[(size_t)MM * DD]; // sampled output split lo
__device__ __nv_bfloat16 g_w1h[DD * NCAT];        // [k][n] stage-1 weights hi
__device__ __nv_bfloat16 g_w1l[DD * NCAT];
__device__ __nv_bfloat16 g_w2h[DD * DD];          // [k][n] proj weights hi
__device__ __nv_bfloat16 g_w2l[DD * DD];

// =================== helpers ===================
__device__ __forceinline__ uint32_t smem_to_u32(const void* p) {
    uint32_t a;
    asm("{ .reg .u64 t; cvta.to.shared.u64 t, %1; cvt.u32.u64 %0, t; }" : "=r"(a) : "l"(p));
    return a;
}
__device__ __forceinline__ void split_bf16(float w, __nv_bfloat16& h, __nv_bfloat16& l) {
    h = __float2bfloat16_rn(w);
    l = __float2bfloat16_rn(w - __bfloat162float(h));
}
__device__ __forceinline__ void cp_async16(uint32_t dst, const void* src) {
    asm volatile("{ .reg .u64 g; cvta.to.global.u64 g, %1; cp.async.cg.shared.global [%0], [g], 16; }"
                 :: "r"(dst), "l"(src));
}
__device__ __forceinline__ void cp_commit() {
    asm volatile("cp.async.commit_group;");
}
__device__ __forceinline__ void ldsm_x4(uint32_t (&r)[4], uint32_t addr) {
    asm volatile("ldmatrix.sync.aligned.m8n8.x4.shared.b16 {%0,%1,%2,%3}, [%4];"
                 : "=r"(r[0]), "=r"(r[1]), "=r"(r[2]), "=r"(r[3]) : "r"(addr));
}
__device__ __forceinline__ void ldsm_x2t(uint32_t (&r)[2], uint32_t addr) {
    asm volatile("ldmatrix.sync.aligned.m8n8.x2.trans.shared.b16 {%0,%1}, [%2];"
                 : "=r"(r[0]), "=r"(r[1]) : "r"(addr));
}
__device__ __forceinline__ void mma_bf16(float (&c)[4], const uint32_t (&a)[4], const uint32_t (&b)[2]) {
    asm volatile("mma.sync.aligned.m16n8k16.row.col.f32.bf16.bf16.f32 "
                 "{%0,%1,%2,%3}, {%4,%5,%6,%7}, {%8,%9}, {%0,%1,%2,%3};"
                 : "+f"(c[0]), "+f"(c[1]), "+f"(c[2]), "+f"(c[3])
                 : "r"(a[0]), "r"(a[1]), "r"(a[2]), "r"(a[3]), "r"(b[0]), "r"(b[1]));
}

// =================== pack kernels ===================
__global__ void pack_x_kernel(const float* __restrict__ x)
{
    int idx = blockIdx.x * blockDim.x + threadIdx.x;   // over MM*DD/4
    if (idx < MM * DD / 4) {
        float4 v = reinterpret_cast<const float4*>(x)[idx];
        __nv_bfloat16 h0, l0, h1, l1, h2, l2, h3, l3;
        split_bf16(v.x, h0, l0); split_bf16(v.y, h1, l1);
        split_bf16(v.z, h2, l2); split_bf16(v.w, h3, l3);
        uint2 ph, pl;
        ph.x = ((uint32_t)__bfloat16_as_ushort(h1) << 16) | __bfloat16_as_ushort(h0);
        ph.y = ((uint32_t)__bfloat16_as_ushort(h3) << 16) | __bfloat16_as_ushort(h2);
        pl.x = ((uint32_t)__bfloat16_as_ushort(l1) << 16) | __bfloat16_as_ushort(l0);
        pl.y = ((uint32_t)__bfloat16_as_ushort(l3) << 16) | __bfloat16_as_ushort(l2);
        reinterpret_cast<uint2*>(g_xh)[idx] = ph;
        reinterpret_cast<uint2*>(g_xl)[idx] = pl;
    }
}

// fused: stage-1 weight concat/split + bias + proj weight split
__global__ void pack_w_kernel(const float* __restrict__ qkv_w, const float* __restrict__ qkv_b,
                              const float* __restrict__ off_w, const float* __restrict__ off_b,
                              const float* __restrict__ attw_w, const float* __restrict__ attw_b,
                              const float* __restrict__ proj_w)
{
    int idx = blockIdx.x * blockDim.x + threadIdx.x;
    if (idx < DD * NCAT) {
        int k = idx / NCAT, n = idx % NCAT;
        float w;
        if (n < 256)      w = qkv_w[k * 768 + 512 + n];
        else if (n < 320) w = off_w[k * 64 + (n - 256)];
        else if (n < 352) w = attw_w[k * 32 + (n - 320)];
        else              w = 0.0f;
        __nv_bfloat16 h, l; split_bf16(w, h, l);
        g_w1h[idx] = h; g_w1l[idx] = l;
    }
    int idx2 = idx - DD * NCAT;
    if (idx2 >= 0 && idx2 < DD * DD) {
        __nv_bfloat16 h, l; split_bf16(proj_w[idx2], h, l);
        g_w2h[idx2] = h; g_w2l[idx2] = l;
    }
    if (idx < NCAT) {
        float bv;
        if (idx < 256)      bv = qkv_b[512 + idx];
        else if (idx < 320) bv = off_b[idx - 256];
        else if (idx < 352) bv = attw_b[idx - 320];
        else                bv = 0.0f;
        g_bcat[idx] = bv;
    }
}

// =================== mma.sync bf16x3 GEMM ===================
// C[M, Nw] = A[M,256] @ B[256, Nw] + bias   (A = Ah+Al, B = Bh+Bl bf16 splits)
// CTA tile 128x64, BK=32, 256 threads, warp tile 32x32 (4x2 warp grid).
// 3-stage cp.async pipeline, ONE barrier per stage.
// A rows padded to 80B (16B multiple — cp.async requires 16B-aligned dst),
// B rows to 144B; both bank-conflict-free for ldmatrix.
#define A_ROW_B   80
#define B_ROW_B   144
#define SM_A_SZ   10240                     // 128*80
#define SM_B_OFF  20480                     // 2 * SM_A_SZ
#define SM_B_SZ   4608                      // 32*144
#define SM_STAGE  29696                     // 20480 + 2*4608
#define N_STAGE   3
#define SMEM_GEMM_SZ (N_STAGE * SM_STAGE)   // 89088

__device__ __forceinline__ void mma_gemm_body(const __nv_bfloat16* __restrict__ Ah,
                                              const __nv_bfloat16* __restrict__ Al,
                                              const __nv_bfloat16* __restrict__ Bh,
                                              const __nv_bfloat16* __restrict__ Bl,
                                              const float* __restrict__ bias,
                                              float* __restrict__ C, int Nw)
{
    extern __shared__ char smem[];
    const uint32_t sm = smem_to_u32(smem);
    const int tid = threadIdx.x;
    const int lane = tid & 31, wid = tid >> 5;
    const int warp_m = wid >> 1, warp_n = wid & 1;
    const int m0 = blockIdx.y * 128, n0 = blockIdx.x * 64;

    // per-thread cp.async chunk assignments (A: 4 chunks, B: 2 chunks of 16B)
    const __nv_bfloat16* a_src[4]; uint32_t a_dst[4];
#pragma unroll
    for (int i = 0; i < 4; ++i) {
        int c = tid + i * 256;
        int mat = c >> 9, cc = c & 511, row = cc >> 2, kc = cc & 3;
        a_src[i] = (mat ? Al : Ah) + (size_t)(m0 + row) * DD + kc * 8;
        a_dst[i] = sm + mat * SM_A_SZ + row * A_ROW_B + kc * 16;
    }
    const __nv_bfloat16* b_src[2]; uint32_t b_dst[2];
#pragma unroll
    for (int j = 0; j < 2; ++j) {
        int c = tid + j * 256;
        int mat = c >> 8, cc = c & 255, row = cc >> 3, nc = cc & 7;
        b_src[j] = (mat ? Bl : Bh) + (size_t)row * Nw + n0 + nc * 8;
        b_dst[j] = sm + SM_B_OFF + mat * SM_B_SZ + row * B_ROW_B + nc * 16;
    }

    float acc[2][4][4];
#pragma unroll
    for (int mt = 0; mt < 2; ++mt)
#pragma unroll
        for (int nt = 0; nt < 4; ++nt)
#pragma unroll
            for (int e = 0; e < 4; ++e) acc[mt][nt][e] = 0.0f;

    auto prefetch = [&](int s, int buf) {
        uint32_t bo = (uint32_t)buf * SM_STAGE;
#pragma unroll
        for (int i = 0; i < 4; ++i) cp_async16(a_dst[i] + bo, a_src[i] + s * 32);
#pragma unroll
        for (int j = 0; j < 2; ++j) cp_async16(b_dst[j] + bo, b_src[j] + (size_t)s * 32 * Nw);
        cp_commit();
    };

    prefetch(0, 0);
    prefetch(1, 1);
    int buf = 0;
    for (int s = 0; s < 8; ++s) {
        if (s < 7) asm volatile("cp.async.wait_group 1;");
        else       asm volatile("cp.async.wait_group 0;");
        __syncthreads();
        // This barrier proves all warps finished computing stage s-1, so
        // buffer (s+2)%3 == (s-1)%3 is reusable — no trailing barrier needed.
        if (s + 2 < 8) prefetch(s + 2, (s + 2) % 3);

        uint32_t base = sm + (uint32_t)buf * SM_STAGE;
#pragma unroll
        for (int k16 = 0; k16 < 2; ++k16) {
            const int kk = k16 * 16;
            uint32_t ah[2][4], al[2][4];
            const int rA = lane & 15, cA = kk + ((lane >> 4) << 3);
#pragma unroll
            for (int mt = 0; mt < 2; ++mt) {
                uint32_t ad = base + (warp_m * 32 + mt * 16 + rA) * A_ROW_B + cA * 2;
                ldsm_x4(ah[mt], ad);
                ldsm_x4(al[mt], ad + SM_A_SZ);
            }
            uint32_t bh[4][2], bl[4][2];
            const int rB = kk + (lane & 15);
#pragma unroll
            for (int nt = 0; nt < 4; ++nt) {
                uint32_t bd = base + SM_B_OFF + rB * B_ROW_B + (warp_n * 32 + nt * 8) * 2;
                ldsm_x2t(bh[nt], bd);
                ldsm_x2t(bl[nt], bd + SM_B_SZ);
            }
#pragma unroll
            for (int mt = 0; mt < 2; ++mt)
#pragma unroll
                for (int nt = 0; nt < 4; ++nt) {
                    mma_bf16(acc[mt][nt], ah[mt], bh[nt]);
                    mma_bf16(acc[mt][nt], al[mt], bh[nt]);
                    mma_bf16(acc[mt][nt], ah[mt], bl[nt]);
                }
        }
        buf = (buf + 1) % 3;
    }

    // epilogue: fp32 + bias, float2 stores
    const int rbase = m0 + warp_m * 32 + (lane >> 2);
    const int cbase = n0 + warp_n * 32 + (lane & 3) * 2;
#pragma unroll
    for (int mt = 0; mt < 2; ++mt) {
#pragma unroll
        for (int nt = 0; nt < 4; ++nt) {
            int col = cbase + nt * 8;
            float b0 = bias[col], b1 = bias[col + 1];
            float2 v0 = make_float2(acc[mt][nt][0] + b0, acc[mt][nt][1] + b1);
            float2 v1 = make_float2(acc[mt][nt][2] + b0, acc[mt][nt][3] + b1);
            *reinterpret_cast<float2*>(C + (size_t)(rbase + mt * 16) * Nw + col) = v0;
            *reinterpret_cast<float2*>(C + (size_t)(rbase + mt * 16 + 8) * Nw + col) = v1;
        }
    }
}

__global__ __launch_bounds__(256, 2) void gemm1_kernel()
{
    mma_gemm_body(g_xh, g_xl, g_w1h, g_w1l, g_bcat, g_y, NCAT);
}

__global__ __launch_bounds__(256, 2) void gemm2_kernel(const float* __restrict__ proj_b,
                                                       float* __restrict__ out)
{
    mma_gemm_body(g_midh, g_midl, g_w2h, g_w2l, proj_b, out, DD);
}

// ---------------- offset/attention prep: one THREAD per (b,n,h) -------------
// Computes tanh offsets + softmax once (was redundantly done by all 32 lanes
// of a warp in the sampler). Stores {gx[4], gy[4], ap[4]} per (b,n,h).
__global__ __launch_bounds__(256) void prep_kernel()
{
    int t = blockIdx.x * blockDim.x + threadIdx.x;   // (b*NN+n)*NH + h
    int h = t & 7;
    int bn = t >> 3;
    int n = bn & (NN - 1);

    const float* yrow = g_y + (size_t)bn * NCAT;

    float offr[8];
#pragma unroll
    for (int i = 0; i < 8; ++i) offr[i] = yrow[256 + h * 8 + i];
    float aw[4];
#pragma unroll
    for (int p = 0; p < NP; ++p) aw[p] = yrow[320 + h * 4 + p];

    float mx = fmaxf(fmaxf(aw[0], aw[1]), fmaxf(aw[2], aw[3]));
    float s = 0.0f;
#pragma unroll
    for (int p = 0; p < NP; ++p) { aw[p] = __expf(aw[p] - mx); s += aw[p]; }
    float inv = 1.0f / s;

    float px = (float)(n & 63);
    float py = (float)(n >> 6);

    float4 GX, GY, AP;
    GX.x = px + 2.0f * tanhf(offr[0]); GY.x = py + 2.0f * tanhf(offr[1]);
    GX.y = px + 2.0f * tanhf(offr[2]); GY.y = py + 2.0f * tanhf(offr[3]);
    GX.z = px + 2.0f * tanhf(offr[4]); GY.z = py + 2.0f * tanhf(offr[5]);
    GX.w = px + 2.0f * tanhf(offr[6]); GY.w = py + 2.0f * tanhf(offr[7]);
    AP.x = aw[0] * inv; AP.y = aw[1] * inv; AP.z = aw[2] * inv; AP.w = aw[3] * inv;

    float4* dst = reinterpret_cast<float4*>(g_prep + (size_t)t * 12);
    dst[0] = GX; dst[1] = GY; dst[2] = AP;
}

// ---------------- deformable sampling: smem-tiled, prep-driven --------------
// One block per (b, h, 16x16 pixel tile). Offsets are 2*tanh in (-2,2), so all
// bilinear corners live in a 20x20 window. Stage window (fp32, zero-filled OOB)
// in smem: gathers become conflict-free LDS (lane = channel).
#define TILE_PX  16
#define WIN      20                         // 16 + 2*2 halo
#define SMEM_SAMP_SZ (WIN * WIN * HD * 4)   // 51200 bytes

__global__ __launch_bounds__(256) void sample_kernel()
{
    extern __shared__ float vt[];           // [WIN*WIN][32]
    const int tid = threadIdx.x;
    const int lane = tid & 31, wid = tid >> 5;

    const int t = blockIdx.x;
    const int tile = t & 15;
    const int h = (t >> 4) & 7;
    const int b = t >> 7;
    const int tx0 = (tile & 3) * TILE_PX;
    const int ty0 = (tile >> 2) * TILE_PX;

    // ---- load 20x20x32 window (zero-filled at image borders) ----
    for (int p = wid; p < WIN * WIN; p += 8) {
        int py = p / WIN, px = p % WIN;
        int gy = ty0 - 2 + py, gx = tx0 - 2 + px;
        float v = 0.0f;
        if (gy >= 0 && gy < 64 && gx >= 0 && gx < 64)
            v = g_y[(size_t)(b * NN + gy * 64 + gx) * NCAT + h * HD + lane];
        vt[p * HD + lane] = v;
    }
    __syncthreads();

    // window-local coordinate base: global - (tx0-2) / (ty0-2)
    const float bx = (float)(2 - tx0);
    const float by = (float)(2 - ty0);

    // ---- compute: warp per pixel (lane = channel), bilinear only ----
    for (int q = wid; q < TILE_PX * TILE_PX; q += 8) {
        int py = q >> 4, px = q & 15;
        int n = (ty0 + py) * 64 + (tx0 + px);

        const float4* pp = reinterpret_cast<const float4*>(
            g_prep + ((size_t)(b * NN + n) * NH + h) * 12);
        float4 GX = pp[0], GY = pp[1], AP = pp[2];

        float gxa[4] = {GX.x, GX.y, GX.z, GX.w};
        float gya[4] = {GY.x, GY.y, GY.z, GY.w};
        float apa[4] = {AP.x, AP.y, AP.z, AP.w};

        float acc = 0.0f;
#pragma unroll
        for (int p = 0; p < NP; ++p) {
            float lgx = gxa[p] + bx;
            float lgy = gya[p] + by;
            float x0f = floorf(lgx), y0f = floorf(lgy);
            int x0 = (int)x0f, y0 = (int)y0f;
            float wx1 = lgx - x0f, wy1 = lgy - y0f;
            float wx0 = 1.0f - wx1, wy0 = 1.0f - wy1;
            float ap = apa[p];

            const float* c00 = vt + (y0 * WIN + x0) * HD + lane;
            float v00 = c00[0];
            float v10 = c00[HD];
            float v01 = c00[WIN * HD];
            float v11 = c00[WIN * HD + HD];
            acc += ap * (wy0 * (wx0 * v00 + wx1 * v10) + wy1 * (wx0 * v01 + wx1 * v11));
        }

        size_t ofs = (size_t)(b * NN + n) * DD + h * HD + lane;
        __nv_bfloat16 hh, ll; split_bf16(acc, hh, ll);
        g_midh[ofs] = hh;
        g_midl[ofs] = ll;
    }
}

// ---------------- launch ----------------
extern "C" void kernel_launch(void* const* d_in, const int* in_sizes, int n_in,
                              void* d_out, int out_size)
{
    const float* x      = (const float*)d_in[0];
    const float* qkv_w  = (const float*)d_in[1];
    const float* qkv_b  = (const float*)d_in[2];
    const float* off_w  = (const float*)d_in[3];
    const float* off_b  = (const float*)d_in[4];
    const float* attw_w = (const float*)d_in[5];
    const float* attw_b = (const float*)d_in[6];
    const float* proj_w = (const float*)d_in[7];
    const float* proj_b = (const float*)d_in[8];
    float* out = (float*)d_out;

    cudaFuncSetAttribute(gemm1_kernel, cudaFuncAttributeMaxDynamicSharedMemorySize, SMEM_GEMM_SZ);
    cudaFuncSetAttribute(gemm2_kernel, cudaFuncAttributeMaxDynamicSharedMemorySize, SMEM_GEMM_SZ);
    cudaFuncSetAttribute(sample_kernel, cudaFuncAttributeMaxDynamicSharedMemorySize, SMEM_SAMP_SZ);

    // 1) split inputs/weights into bf16 hi/lo
    pack_x_kernel<<<(MM * DD / 4 + 255) / 256, 256>>>(x);
    pack_w_kernel<<<(DD * NCAT + DD * DD + 255) / 256, 256>>>(
        qkv_w, qkv_b, off_w, off_b, attw_w, attw_b, proj_w);

    // 2) stage-1 GEMM (mma.sync bf16x3): X[32768,256] @ Wcat[256,384] -> g_y
    gemm1_kernel<<<dim3(NCAT / 64, MM / 128), 256, SMEM_GEMM_SZ>>>();

    // 3a) per-(b,n,h) scalar prep: tanh offsets + softmax (once, not per lane)
    prep_kernel<<<MM * NH / 256, 256>>>();

    // 3b) deformable sampling, smem-tiled: (b, h, 16x16 tile) per block
    sample_kernel<<<BB * NH * 16, 256, SMEM_SAMP_SZ>>>();

    // 4) output projection (mma.sync bf16x3): mid @ proj_w[256,256] + b -> out
    gemm2_kernel<<<dim3(DD / 64, MM / 128), 256, SMEM_GEMM_SZ>>>(proj_b, out);
}